// round 1
// baseline (speedup 1.0000x reference)
#include <cuda_runtime.h>
#include <math.h>

#define BATCH 32768
#define H1DIM 400

// Scratch (no cudaMalloc allowed)
__device__ float g_h1[BATCH * H1DIM];
__device__ float g_h3[BATCH * H1DIM];
__device__ float g_z[BATCH * 20];

// ---------------------------------------------------------------------------
// Activation functors
// ---------------------------------------------------------------------------
template <int ACT>
__device__ __forceinline__ float act_apply(float v) {
    if (ACT == 1) return fmaxf(v, 0.f);                // relu
    if (ACT == 2) return expf(v);                      // exp
    if (ACT == 3) return 1.f / (1.f + expf(-v));       // sigmoid
    return v;                                          // identity
}

// ---------------------------------------------------------------------------
// SGEMM: C[M,N] = act(A[M,K] @ B[K,N] + bias[N])
// 128x128 block tile, BK=8, 256 threads, 8x8 microtile, double buffered.
// Requirements: M % 128 == 0, K % 8 == 0. N arbitrary (guarded).
// ---------------------------------------------------------------------------
template <int ACT>
__global__ void __launch_bounds__(256)
sgemm_bias_act(const float* __restrict__ A, const float* __restrict__ Bw,
               const float* __restrict__ bias, float* __restrict__ C,
               int M, int N, int K) {
    constexpr int BM = 128, BN = 128, BK = 8, TM = 8, TN = 8;
    __shared__ float As[2][BK][BM];
    __shared__ float Bs[2][BK][BN];

    const int tid = threadIdx.x;
    const int tx = tid & 15, ty = tid >> 4;
    const int rowBase = blockIdx.y * BM, colBase = blockIdx.x * BN;
    const int aRow = tid >> 1, aK4 = (tid & 1) * 4;
    const int bRow = tid >> 5, bCol4 = (tid & 31) * 4;
    const int bc = colBase + bCol4;

    float acc[TM][TN];
#pragma unroll
    for (int i = 0; i < TM; i++)
#pragma unroll
        for (int j = 0; j < TN; j++) acc[i][j] = 0.f;

    const int nTiles = K / BK;
    const float* Aptr = A + (size_t)(rowBase + aRow) * K + aK4;

    auto loadB = [&](int k0) -> float4 {
        const float* p = Bw + (size_t)(k0 + bRow) * N;
        if (bc + 3 < N) return *(const float4*)(p + bc);
        float4 v = make_float4(0.f, 0.f, 0.f, 0.f);
        if (bc + 0 < N) v.x = p[bc + 0];
        if (bc + 1 < N) v.y = p[bc + 1];
        if (bc + 2 < N) v.z = p[bc + 2];
        return v;
    };

    {
        float4 av = *(const float4*)(Aptr);
        float4 bv = loadB(0);
        As[0][aK4 + 0][aRow] = av.x;
        As[0][aK4 + 1][aRow] = av.y;
        As[0][aK4 + 2][aRow] = av.z;
        As[0][aK4 + 3][aRow] = av.w;
        *(float4*)&Bs[0][bRow][bCol4] = bv;
    }
    __syncthreads();

    int buf = 0;
    for (int t = 0; t < nTiles; t++) {
        float4 av, bv;
        const bool more = (t + 1 < nTiles);
        if (more) {
            av = *(const float4*)(Aptr + (t + 1) * BK);
            bv = loadB((t + 1) * BK);
        }
#pragma unroll
        for (int k = 0; k < BK; k++) {
            float ra[TM], rb[TN];
            *(float4*)&ra[0] = *(const float4*)&As[buf][k][ty * TM];
            *(float4*)&ra[4] = *(const float4*)&As[buf][k][ty * TM + 4];
            *(float4*)&rb[0] = *(const float4*)&Bs[buf][k][tx * TN];
            *(float4*)&rb[4] = *(const float4*)&Bs[buf][k][tx * TN + 4];
#pragma unroll
            for (int i = 0; i < TM; i++)
#pragma unroll
                for (int j = 0; j < TN; j++)
                    acc[i][j] = fmaf(ra[i], rb[j], acc[i][j]);
        }
        if (more) {
            int nb = buf ^ 1;
            As[nb][aK4 + 0][aRow] = av.x;
            As[nb][aK4 + 1][aRow] = av.y;
            As[nb][aK4 + 2][aRow] = av.z;
            As[nb][aK4 + 3][aRow] = av.w;
            *(float4*)&Bs[nb][bRow][bCol4] = bv;
        }
        __syncthreads();
        buf ^= 1;
    }

    // epilogue
#pragma unroll
    for (int i = 0; i < TM; i++) {
        int rr = rowBase + ty * TM + i;
        float* Cr = C + (size_t)rr * N;
#pragma unroll
        for (int j = 0; j < TN; j += 4) {
            int cc = colBase + tx * TN + j;
            if (cc + 3 < N) {
                float4 bv = *(const float4*)(bias + cc);
                float4 v;
                v.x = act_apply<ACT>(acc[i][j + 0] + bv.x);
                v.y = act_apply<ACT>(acc[i][j + 1] + bv.y);
                v.z = act_apply<ACT>(acc[i][j + 2] + bv.z);
                v.w = act_apply<ACT>(acc[i][j + 3] + bv.w);
                *(float4*)(Cr + cc) = v;
            } else {
#pragma unroll
                for (int q = 0; q < 4; q++)
                    if (cc + q < N)
                        Cr[cc + q] = act_apply<ACT>(acc[i][j + q] + bias[cc + q]);
            }
        }
    }
}

// ---------------------------------------------------------------------------
// Per-row kernel: a-logits -> softmax -> inverse-CDF idx -> gather ->
// LU solve (partial pivoting, lane i owns row i in registers) ->
// z = Q (eigen .* y) + mu
// One warp per row, 8 warps per block.
// ---------------------------------------------------------------------------
__global__ void __launch_bounds__(256)
solve_kernel(const float* __restrict__ Wa, const float* __restrict__ ba,
             const float* __restrict__ u, const float* __restrict__ eps,
             const float* __restrict__ h1, const float* __restrict__ outQ,
             const float* __restrict__ outMu, const float* __restrict__ outEig,
             float* __restrict__ outA, float* __restrict__ z) {
    __shared__ float Qs[8][400];
    const unsigned FULL = 0xffffffffu;
    const int w = threadIdx.x >> 5, lane = threadIdx.x & 31;
    const int row = blockIdx.x * 8 + w;

    // --- a logits: 5 dots of length 400 ---
    float s0 = 0, s1 = 0, s2 = 0, s3 = 0, s4 = 0;
    const float* hr = h1 + (size_t)row * 400;
    for (int k = lane; k < 400; k += 32) {
        float h = hr[k];
        const float* wk = Wa + k * 5;
        s0 = fmaf(h, wk[0], s0);
        s1 = fmaf(h, wk[1], s1);
        s2 = fmaf(h, wk[2], s2);
        s3 = fmaf(h, wk[3], s3);
        s4 = fmaf(h, wk[4], s4);
    }
#pragma unroll
    for (int off = 16; off; off >>= 1) {
        s0 += __shfl_xor_sync(FULL, s0, off);
        s1 += __shfl_xor_sync(FULL, s1, off);
        s2 += __shfl_xor_sync(FULL, s2, off);
        s3 += __shfl_xor_sync(FULL, s3, off);
        s4 += __shfl_xor_sync(FULL, s4, off);
    }
    s0 += ba[0]; s1 += ba[1]; s2 += ba[2]; s3 += ba[3]; s4 += ba[4];
    float mx = fmaxf(fmaxf(fmaxf(s0, s1), fmaxf(s2, s3)), s4);
    float e0 = expf(s0 - mx), e1 = expf(s1 - mx), e2 = expf(s2 - mx),
          e3 = expf(s3 - mx), e4 = expf(s4 - mx);
    float inv = 1.f / (e0 + e1 + e2 + e3 + e4);
    float av[5] = {e0 * inv, e1 * inv, e2 * inv, e3 * inv, e4 * inv};
    if (lane == 0) {
        float* ar = outA + (size_t)row * 5;
        ar[0] = av[0]; ar[1] = av[1]; ar[2] = av[2]; ar[3] = av[3]; ar[4] = av[4];
    }

    // --- categorical idx via inverse CDF (argmax-of-bool semantics) ---
    float uu = u[row];
    int idx = 0;
    bool found = false;
    float c = 0.f;
#pragma unroll
    for (int j = 0; j < 5; j++) {
        c += av[j];
        if (!found && uu < c) { idx = j; found = true; }
    }
    // all-false -> idx stays 0 (matches jnp.argmax)

    // --- gather this_Q into smem (coalesced) ---
    const float* Qr = outQ + (size_t)row * 2000 + idx * 400;
    for (int k = lane; k < 400; k += 32) Qs[w][k] = Qr[k];
    __syncwarp();

    float o[20], r[20];
    float rhs = 0.f, eig = 0.f, mui = 0.f;
    if (lane < 20) {
#pragma unroll
        for (int j = 0; j < 20; j++) o[j] = Qs[w][lane * 20 + j];
        rhs = eps[(size_t)row * 20 + lane];
        eig = outEig[(size_t)row * 100 + idx * 20 + lane];
        mui = outMu[(size_t)row * 100 + idx * 20 + lane];
    } else {
#pragma unroll
        for (int j = 0; j < 20; j++) o[j] = 0.f;
    }
#pragma unroll
    for (int j = 0; j < 20; j++) r[j] = o[j];

    // --- LU with partial pivoting, fully unrolled (registers only) ---
#pragma unroll
    for (int k = 0; k < 20; k++) {
        float key = (lane >= k && lane < 20) ? fabsf(r[k]) : -1.0f;
        int pi = lane;
#pragma unroll
        for (int off = 16; off; off >>= 1) {
            float ok = __shfl_xor_sync(FULL, key, off);
            int oi = __shfl_xor_sync(FULL, pi, off);
            if (ok > key || (ok == key && oi < pi)) { key = ok; pi = oi; }
        }
        if (pi != k) {  // warp-uniform
            int partner = (lane == k) ? pi : ((lane == pi) ? k : lane);
#pragma unroll
            for (int j = 0; j < 20; j++) r[j] = __shfl_sync(FULL, r[j], partner);
            rhs = __shfl_sync(FULL, rhs, partner);
        }
        float akk = __shfl_sync(FULL, r[k], k);
        float m = (lane > k && lane < 20) ? r[k] / akk : 0.0f;
        float rk = __shfl_sync(FULL, rhs, k);
        rhs = fmaf(-m, rk, rhs);
#pragma unroll
        for (int j = k + 1; j < 20; j++) {
            float akj = __shfl_sync(FULL, r[j], k);
            r[j] = fmaf(-m, akj, r[j]);
        }
    }

    // --- back substitution ---
    float y = 0.f;
#pragma unroll
    for (int k = 19; k >= 0; k--) {
        float num = __shfl_sync(FULL, rhs, k);
        float akk = __shfl_sync(FULL, r[k], k);
        float yk = num / akk;
        if (lane == k) y = yk;
        if (lane < k) rhs = fmaf(-r[k], yk, rhs);
    }

    // --- z = Q (eigen .* y) + mu ---
    float wv = eig * y;
    float zv = mui;
#pragma unroll
    for (int j = 0; j < 20; j++) {
        float wj = __shfl_sync(FULL, wv, j);
        zv = fmaf(o[j], wj, zv);
    }
    if (lane < 20) z[(size_t)row * 20 + lane] = zv;
}

// ---------------------------------------------------------------------------
// h3 = relu(z @ W3 + b3): [B,20] @ [20,400]. Each thread owns one output
// column (W3 column in registers), iterates 32 rows staged in smem.
// ---------------------------------------------------------------------------
__global__ void __launch_bounds__(128)
h3_kernel(const float* __restrict__ z, const float* __restrict__ W3,
          const float* __restrict__ b3, float* __restrict__ h3) {
    __shared__ float zs[32 * 20];
    const int col = blockIdx.x * 128 + threadIdx.x;
    const int row0 = blockIdx.y * 32;
    for (int i = threadIdx.x; i < 32 * 20; i += 128)
        zs[i] = z[(size_t)row0 * 20 + i];
    __syncthreads();

    if (col < 400) {
        float wcol[20];
#pragma unroll
        for (int k = 0; k < 20; k++) wcol[k] = W3[k * 400 + col];
        float bias = b3[col];
        for (int rr = 0; rr < 32; rr++) {
            float acc = bias;
#pragma unroll
            for (int k = 0; k < 20; k++) acc = fmaf(zs[rr * 20 + k], wcol[k], acc);
            h3[(size_t)(row0 + rr) * 400 + col] = fmaxf(acc, 0.f);
        }
    }
}

// ---------------------------------------------------------------------------
// Launch
// ---------------------------------------------------------------------------
extern "C" void kernel_launch(void* const* d_in, const int* in_sizes, int n_in,
                              void* d_out, int out_size) {
    const float* x   = (const float*)d_in[0];
    const float* u   = (const float*)d_in[1];
    const float* eps = (const float*)d_in[2];
    const float* W1  = (const float*)d_in[3];
    const float* b1  = (const float*)d_in[4];
    const float* Wmu = (const float*)d_in[5];
    const float* bmu = (const float*)d_in[6];
    const float* WQ  = (const float*)d_in[7];
    const float* bQ  = (const float*)d_in[8];
    const float* Wa  = (const float*)d_in[9];
    const float* ba  = (const float*)d_in[10];
    const float* We  = (const float*)d_in[11];
    const float* be  = (const float*)d_in[12];
    const float* W3  = (const float*)d_in[13];
    const float* b3  = (const float*)d_in[14];
    const float* W4  = (const float*)d_in[15];
    const float* b4  = (const float*)d_in[16];

    float* out = (float*)d_out;
    float* out_recon = out;
    float* out_mu    = out_recon + (size_t)BATCH * 784;
    float* out_Q     = out_mu    + (size_t)BATCH * 100;
    float* out_a     = out_Q     + (size_t)BATCH * 2000;
    float* out_eig   = out_a     + (size_t)BATCH * 5;

    float *h1p, *h3p, *zp;
    cudaGetSymbolAddress((void**)&h1p, g_h1);
    cudaGetSymbolAddress((void**)&h3p, g_h3);
    cudaGetSymbolAddress((void**)&zp, g_z);

    dim3 blk(256);
    // h1 = relu(x@W1 + b1)
    sgemm_bias_act<1><<<dim3(4, 256), blk>>>(x, W1, b1, h1p, BATCH, 400, 784);
    // Q = exp(h1@WQ + bQ)
    sgemm_bias_act<2><<<dim3(16, 256), blk>>>(h1p, WQ, bQ, out_Q, BATCH, 2000, 400);
    // mu = h1@Wmu + bmu
    sgemm_bias_act<0><<<dim3(1, 256), blk>>>(h1p, Wmu, bmu, out_mu, BATCH, 100, 400);
    // eigen = exp(h1@We + be)
    sgemm_bias_act<2><<<dim3(1, 256), blk>>>(h1p, We, be, out_eig, BATCH, 100, 400);
    // softmax/idx/LU-solve/z
    solve_kernel<<<BATCH / 8, 256>>>(Wa, ba, u, eps, h1p, out_Q, out_mu,
                                     out_eig, out_a, zp);
    // h3 = relu(z@W3 + b3)
    h3_kernel<<<dim3(4, BATCH / 32), 128>>>(zp, W3, b3, h3p);
    // recon = sigmoid(h3@W4 + b4)
    sgemm_bias_act<3><<<dim3(7, 256), blk>>>(h3p, W4, b4, out_recon, BATCH, 784, 400);
}

// round 3
// speedup vs baseline: 2.1139x; 2.1139x over previous
#include <cuda_runtime.h>
#include <cuda_bf16.h>
#include <math.h>
#include <stdint.h>

#define BATCH 32768
#define KP_X 832   // 784 padded to 26*32
#define KP_H 448   // 400 padded to 14*32

// ---------------- scratch (__device__ globals; no cudaMalloc allowed) ------
__device__ __align__(256) __nv_bfloat16 g_xhi[BATCH * KP_X];
__device__ __align__(256) __nv_bfloat16 g_xlo[BATCH * KP_X];
__device__ __align__(256) __nv_bfloat16 g_h1hi[BATCH * KP_H];
__device__ __align__(256) __nv_bfloat16 g_h1lo[BATCH * KP_H];
__device__ __align__(256) __nv_bfloat16 g_h3hi[BATCH * KP_H];
__device__ __align__(256) __nv_bfloat16 g_h3lo[BATCH * KP_H];
__device__ __align__(256) __nv_bfloat16 g_B1hi[400 * KP_X];
__device__ __align__(256) __nv_bfloat16 g_B1lo[400 * KP_X];
__device__ __align__(256) __nv_bfloat16 g_BQhi[2000 * KP_H];
__device__ __align__(256) __nv_bfloat16 g_BQlo[2000 * KP_H];
__device__ __align__(256) __nv_bfloat16 g_Bmuhi[128 * KP_H];
__device__ __align__(256) __nv_bfloat16 g_Bmulo[128 * KP_H];
__device__ __align__(256) __nv_bfloat16 g_Behi[128 * KP_H];
__device__ __align__(256) __nv_bfloat16 g_Belo[128 * KP_H];
__device__ __align__(256) __nv_bfloat16 g_B4hi[784 * KP_H];
__device__ __align__(256) __nv_bfloat16 g_B4lo[784 * KP_H];
__device__ float g_z[BATCH * 20];

// ---------------- helpers --------------------------------------------------
__device__ __forceinline__ uint32_t smem_u32(const void* p) {
    uint32_t a;
    asm("{ .reg .u64 t; cvta.to.shared.u64 t, %1; cvt.u32.u64 %0, t; }"
        : "=r"(a) : "l"(p));
    return a;
}
__device__ __forceinline__ void split2(float v, __nv_bfloat16& hi, __nv_bfloat16& lo) {
    hi = __float2bfloat16(v);
    lo = __float2bfloat16(v - __bfloat162float(hi));
}
template <int ACT>
__device__ __forceinline__ float act_apply(float v) {
    if (ACT == 1) return fmaxf(v, 0.f);
    if (ACT == 2) return expf(v);
    if (ACT == 3) return 1.f / (1.f + expf(-v));
    return v;
}

#define CP_ASYNC16(dst, src, sz) \
    asm volatile("cp.async.cg.shared.global [%0], [%1], 16, %2;" \
                 :: "r"(dst), "l"(src), "r"(sz) : "memory")
#define CP_COMMIT() asm volatile("cp.async.commit_group;" ::: "memory")
template <int NW>
__device__ __forceinline__ void cp_wait() {
    asm volatile("cp.async.wait_group %0;" :: "n"(NW) : "memory");
}

__device__ __forceinline__ void ldsm4(uint32_t* r, uint32_t addr) {
    asm volatile("ldmatrix.sync.aligned.m8n8.x4.shared.b16 {%0,%1,%2,%3}, [%4];"
                 : "=r"(r[0]), "=r"(r[1]), "=r"(r[2]), "=r"(r[3]) : "r"(addr));
}
__device__ __forceinline__ void mma16816(float* d, const uint32_t* a, const uint32_t* b) {
    asm volatile(
        "mma.sync.aligned.m16n8k16.row.col.f32.bf16.bf16.f32 "
        "{%0,%1,%2,%3}, {%4,%5,%6,%7}, {%8,%9}, {%0,%1,%2,%3};"
        : "+f"(d[0]), "+f"(d[1]), "+f"(d[2]), "+f"(d[3])
        : "r"(a[0]), "r"(a[1]), "r"(a[2]), "r"(a[3]), "r"(b[0]), "r"(b[1]));
}

// Row stride 64B (32 bf16); XOR-swizzle 16B chunks so ldmatrix + cp.async are
// conflict-free: chunkpos = chunk ^ ((row>>1)&3)
__device__ __forceinline__ uint32_t swoff(int row, int chunk) {
    return ((uint32_t)row << 6) + ((uint32_t)((chunk ^ ((row >> 1) & 3))) << 4);
}

// ---------------- split kernels -------------------------------------------
__global__ void split_a(const float* __restrict__ A, __nv_bfloat16* __restrict__ hi,
                        __nv_bfloat16* __restrict__ lo, int K, int Kp, long total) {
    long i = (long)blockIdx.x * blockDim.x + threadIdx.x;
    if (i >= total) return;
    int k = (int)(i % Kp);
    long r = i / Kp;
    float v = (k < K) ? A[r * K + k] : 0.f;
    __nv_bfloat16 h, l;
    split2(v, h, l);
    hi[i] = h;
    lo[i] = l;
}

// W [K,N] fp32 -> out [Np,Kp] bf16 (transposed, padded)
__global__ void split_w(const float* __restrict__ W, __nv_bfloat16* __restrict__ hi,
                        __nv_bfloat16* __restrict__ lo, int K, int N, int Kp, int Np) {
    long i = (long)blockIdx.x * blockDim.x + threadIdx.x;
    if (i >= (long)Np * Kp) return;
    int k = (int)(i % Kp);
    long n = i / Kp;
    float v = (k < K && n < N) ? W[(size_t)k * N + n] : 0.f;
    __nv_bfloat16 h, l;
    split2(v, h, l);
    hi[i] = h;
    lo[i] = l;
}

// ---------------- 3-term bf16 split GEMM on mma.sync -----------------------
// C[M,N] = act((Ahi+Alo)[M,Kp] @ ((Bhi+Blo)[N,Kp])^T + bias)
// 128x128x32 CTA tile, 8 warps (4x2), warp tile 32x64, 3-stage cp.async.
#define STAGES 3
#define STAGE_BYTES 32768
#define GEMM_SMEM (STAGES * STAGE_BYTES)

template <int ACT, bool SPLIT_OUT>
__global__ void __launch_bounds__(256)
mma_gemm(const __nv_bfloat16* __restrict__ Ahi, const __nv_bfloat16* __restrict__ Alo,
         const __nv_bfloat16* __restrict__ Bhi, const __nv_bfloat16* __restrict__ Blo,
         const float* __restrict__ bias, float* __restrict__ C,
         __nv_bfloat16* __restrict__ outHi, __nv_bfloat16* __restrict__ outLo,
         int N, int Kp, int ldOut) {
    extern __shared__ char smem[];
    const uint32_t sbase = smem_u32(smem);
    const int tid = threadIdx.x, wid = tid >> 5, lane = tid & 31;
    const int wm = wid >> 1, wn = wid & 1;
    const int rowBase = blockIdx.y * 128, colBase = blockIdx.x * 128;
    const int NC = Kp >> 5;

    float acc[2][8][4];
#pragma unroll
    for (int i = 0; i < 2; i++)
#pragma unroll
        for (int j = 0; j < 8; j++)
#pragma unroll
            for (int q = 0; q < 4; q++) acc[i][j][q] = 0.f;

    auto load_stage = [&](int c, int stg) {
        const int kBase = c << 5;
        const uint32_t sb = sbase + stg * STAGE_BYTES;
#pragma unroll
        for (int t = 0; t < 4; t++) {
            const __nv_bfloat16* P = (t == 0) ? Ahi : (t == 1) ? Alo
                                   : (t == 2) ? Bhi : Blo;
            const bool isB = (t >= 2);
#pragma unroll
            for (int i = 0; i < 2; i++) {
                int cid = tid + i * 256;          // 0..511
                int row = cid >> 2, ch = cid & 3;
                uint32_t dst = sb + t * 8192 + swoff(row, ch);
                int gr, sz = 16;
                if (isB) {
                    gr = colBase + row;
                    if (gr >= N) { gr = 0; sz = 0; }
                } else {
                    gr = rowBase + row;
                }
                const void* src = P + (size_t)gr * Kp + kBase + ch * 8;
                CP_ASYNC16(dst, src, sz);
            }
        }
    };

    load_stage(0, 0);
    CP_COMMIT();
    load_stage(1, 1);
    CP_COMMIT();

    for (int c = 0; c < NC; c++) {
        cp_wait<STAGES - 2>();
        __syncthreads();
        if (c + STAGES - 1 < NC) {
            load_stage(c + STAGES - 1, (c + STAGES - 1) % STAGES);
            CP_COMMIT();
        }
        const uint32_t sb = sbase + (c % STAGES) * STAGE_BYTES;
#pragma unroll
        for (int kk = 0; kk < 2; kk++) {
            uint32_t ahi[2][4], alo[2][4];
#pragma unroll
            for (int mi = 0; mi < 2; mi++) {
                int row = wm * 32 + mi * 16 + (lane & 15);
                int ch = kk * 2 + (lane >> 4);
                uint32_t o = swoff(row, ch);
                ldsm4(ahi[mi], sb + o);
                ldsm4(alo[mi], sb + 8192 + o);
            }
#pragma unroll
            for (int bi = 0; bi < 4; bi++) {
                int row = wn * 64 + bi * 16 + (lane & 7) + ((lane >> 4) << 3);
                int ch = kk * 2 + ((lane >> 3) & 1);
                uint32_t o = swoff(row, ch);
                uint32_t bhi[4], blo[4];
                ldsm4(bhi, sb + 16384 + o);
                ldsm4(blo, sb + 24576 + o);
#pragma unroll
                for (int mi = 0; mi < 2; mi++) {
                    mma16816(acc[mi][2 * bi],     ahi[mi], bhi);
                    mma16816(acc[mi][2 * bi + 1], ahi[mi], bhi + 2);
                    mma16816(acc[mi][2 * bi],     alo[mi], bhi);
                    mma16816(acc[mi][2 * bi + 1], alo[mi], bhi + 2);
                    mma16816(acc[mi][2 * bi],     ahi[mi], blo);
                    mma16816(acc[mi][2 * bi + 1], ahi[mi], blo + 2);
                }
            }
        }
    }

    // ---------------- epilogue ----------------
#pragma unroll
    for (int mi = 0; mi < 2; mi++) {
#pragma unroll
        for (int ni = 0; ni < 8; ni++) {
            const float* a4 = acc[mi][ni];
            const int r0 = rowBase + wm * 32 + mi * 16 + (lane >> 2);
            const int col = colBase + wn * 64 + ni * 8 + ((lane & 3) << 1);
            float b0 = (col < N) ? bias[col] : 0.f;
            float b1 = (col + 1 < N) ? bias[col + 1] : 0.f;
#pragma unroll
            for (int h = 0; h < 2; h++) {
                const size_t row = (size_t)(r0 + h * 8);
                const float v0 = act_apply<ACT>(a4[2 * h + 0] + b0);
                const float v1 = act_apply<ACT>(a4[2 * h + 1] + b1);
                if (SPLIT_OUT) {
                    if (col < N) {
                        __nv_bfloat16 hh, ll;
                        split2(v0, hh, ll);
                        outHi[row * ldOut + col] = hh;
                        outLo[row * ldOut + col] = ll;
                        if (col + 1 < N) {
                            split2(v1, hh, ll);
                            outHi[row * ldOut + col + 1] = hh;
                            outLo[row * ldOut + col + 1] = ll;
                        } else if (col + 1 < ldOut) {
                            outHi[row * ldOut + col + 1] = __float2bfloat16(0.f);
                            outLo[row * ldOut + col + 1] = __float2bfloat16(0.f);
                        }
                    } else if (col < ldOut) {
                        outHi[row * ldOut + col] = __float2bfloat16(0.f);
                        outLo[row * ldOut + col] = __float2bfloat16(0.f);
                        if (col + 1 < ldOut) {
                            outHi[row * ldOut + col + 1] = __float2bfloat16(0.f);
                            outLo[row * ldOut + col + 1] = __float2bfloat16(0.f);
                        }
                    }
                } else {
                    if (col < N) C[row * ldOut + col] = v0;
                    if (col + 1 < N) C[row * ldOut + col + 1] = v1;
                }
            }
        }
    }
}

// ---------------- per-row solve kernel ------------------------------------
__global__ void __launch_bounds__(256)
solve_kernel(const float* __restrict__ Wa, const float* __restrict__ ba,
             const float* __restrict__ u, const float* __restrict__ eps,
             const __nv_bfloat16* __restrict__ h1hi, const __nv_bfloat16* __restrict__ h1lo,
             const float* __restrict__ outQ, const float* __restrict__ outMu,
             const float* __restrict__ outEig, float* __restrict__ outA,
             float* __restrict__ z) {
    __shared__ float Qs[8][400];
    const unsigned FULL = 0xffffffffu;
    const int w = threadIdx.x >> 5, lane = threadIdx.x & 31;
    const int row = blockIdx.x * 8 + w;

    float s0 = 0, s1 = 0, s2 = 0, s3 = 0, s4 = 0;
    const __nv_bfloat16* hh = h1hi + (size_t)row * KP_H;
    const __nv_bfloat16* hl = h1lo + (size_t)row * KP_H;
    for (int k = lane; k < 400; k += 32) {
        float h = __bfloat162float(hh[k]) + __bfloat162float(hl[k]);
        const float* wk = Wa + k * 5;
        s0 = fmaf(h, wk[0], s0);
        s1 = fmaf(h, wk[1], s1);
        s2 = fmaf(h, wk[2], s2);
        s3 = fmaf(h, wk[3], s3);
        s4 = fmaf(h, wk[4], s4);
    }
#pragma unroll
    for (int off = 16; off; off >>= 1) {
        s0 += __shfl_xor_sync(FULL, s0, off);
        s1 += __shfl_xor_sync(FULL, s1, off);
        s2 += __shfl_xor_sync(FULL, s2, off);
        s3 += __shfl_xor_sync(FULL, s3, off);
        s4 += __shfl_xor_sync(FULL, s4, off);
    }
    s0 += ba[0]; s1 += ba[1]; s2 += ba[2]; s3 += ba[3]; s4 += ba[4];
    float mx = fmaxf(fmaxf(fmaxf(s0, s1), fmaxf(s2, s3)), s4);
    float e0 = expf(s0 - mx), e1 = expf(s1 - mx), e2 = expf(s2 - mx),
          e3 = expf(s3 - mx), e4 = expf(s4 - mx);
    float inv = 1.f / (e0 + e1 + e2 + e3 + e4);
    float av[5] = {e0 * inv, e1 * inv, e2 * inv, e3 * inv, e4 * inv};
    if (lane == 0) {
        float* ar = outA + (size_t)row * 5;
        ar[0] = av[0]; ar[1] = av[1]; ar[2] = av[2]; ar[3] = av[3]; ar[4] = av[4];
    }

    float uu = u[row];
    int idx = 0;
    bool found = false;
    float c = 0.f;
#pragma unroll
    for (int j = 0; j < 5; j++) {
        c += av[j];
        if (!found && uu < c) { idx = j; found = true; }
    }

    const float* Qr = outQ + (size_t)row * 2000 + idx * 400;
    for (int k = lane; k < 400; k += 32) Qs[w][k] = Qr[k];
    __syncwarp();

    float o[20], r[20];
    float rhs = 0.f, eig = 0.f, mui = 0.f;
    if (lane < 20) {
#pragma unroll
        for (int j = 0; j < 20; j++) o[j] = Qs[w][lane * 20 + j];
        rhs = eps[(size_t)row * 20 + lane];
        eig = outEig[(size_t)row * 100 + idx * 20 + lane];
        mui = outMu[(size_t)row * 100 + idx * 20 + lane];
    } else {
#pragma unroll
        for (int j = 0; j < 20; j++) o[j] = 0.f;
    }
#pragma unroll
    for (int j = 0; j < 20; j++) r[j] = o[j];

#pragma unroll
    for (int k = 0; k < 20; k++) {
        float key = (lane >= k && lane < 20) ? fabsf(r[k]) : -1.0f;
        int pi = lane;
#pragma unroll
        for (int off = 16; off; off >>= 1) {
            float ok = __shfl_xor_sync(FULL, key, off);
            int oi = __shfl_xor_sync(FULL, pi, off);
            if (ok > key || (ok == key && oi < pi)) { key = ok; pi = oi; }
        }
        if (pi != k) {
            int partner = (lane == k) ? pi : ((lane == pi) ? k : lane);
#pragma unroll
            for (int j = 0; j < 20; j++) r[j] = __shfl_sync(FULL, r[j], partner);
            rhs = __shfl_sync(FULL, rhs, partner);
        }
        float akk = __shfl_sync(FULL, r[k], k);
        float m = (lane > k && lane < 20) ? r[k] / akk : 0.0f;
        float rk = __shfl_sync(FULL, rhs, k);
        rhs = fmaf(-m, rk, rhs);
#pragma unroll
        for (int j = k + 1; j < 20; j++) {
            float akj = __shfl_sync(FULL, r[j], k);
            r[j] = fmaf(-m, akj, r[j]);
        }
    }

    float y = 0.f;
#pragma unroll
    for (int k = 19; k >= 0; k--) {
        float num = __shfl_sync(FULL, rhs, k);
        float akk = __shfl_sync(FULL, r[k], k);
        float yk = num / akk;
        if (lane == k) y = yk;
        if (lane < k) rhs = fmaf(-r[k], yk, rhs);
    }

    float wv = eig * y;
    float zv = mui;
#pragma unroll
    for (int j = 0; j < 20; j++) {
        float wj = __shfl_sync(FULL, wv, j);
        zv = fmaf(o[j], wj, zv);
    }
    if (lane < 20) z[(size_t)row * 20 + lane] = zv;
}

// ---------------- h3 = relu(z@W3+b3) -> bf16 hi/lo (pads cols 400..447) ---
__global__ void __launch_bounds__(128)
h3_kernel(const float* __restrict__ z, const float* __restrict__ W3,
          const float* __restrict__ b3, __nv_bfloat16* __restrict__ h3hi,
          __nv_bfloat16* __restrict__ h3lo) {
    __shared__ float zs[32 * 20];
    const int col = blockIdx.x * 128 + threadIdx.x;
    const int row0 = blockIdx.y * 32;
    for (int i = threadIdx.x; i < 32 * 20; i += 128)
        zs[i] = z[(size_t)row0 * 20 + i];
    __syncthreads();

    if (col < KP_H) {
        if (col < 400) {
            float wcol[20];
#pragma unroll
            for (int k = 0; k < 20; k++) wcol[k] = W3[k * 400 + col];
            float bias = b3[col];
            for (int rr = 0; rr < 32; rr++) {
                float acc = bias;
#pragma unroll
                for (int k = 0; k < 20; k++)
                    acc = fmaf(zs[rr * 20 + k], wcol[k], acc);
                float v = fmaxf(acc, 0.f);
                __nv_bfloat16 h, l;
                split2(v, h, l);
                h3hi[(size_t)(row0 + rr) * KP_H + col] = h;
                h3lo[(size_t)(row0 + rr) * KP_H + col] = l;
            }
        } else {
            for (int rr = 0; rr < 32; rr++) {
                h3hi[(size_t)(row0 + rr) * KP_H + col] = __float2bfloat16(0.f);
                h3lo[(size_t)(row0 + rr) * KP_H + col] = __float2bfloat16(0.f);
            }
        }
    }
}

// ---------------- launch ---------------------------------------------------
extern "C" void kernel_launch(void* const* d_in, const int* in_sizes, int n_in,
                              void* d_out, int out_size) {
    const float* x   = (const float*)d_in[0];
    const float* u   = (const float*)d_in[1];
    const float* eps = (const float*)d_in[2];
    const float* W1  = (const float*)d_in[3];
    const float* b1  = (const float*)d_in[4];
    const float* Wmu = (const float*)d_in[5];
    const float* bmu = (const float*)d_in[6];
    const float* WQ  = (const float*)d_in[7];
    const float* bQ  = (const float*)d_in[8];
    const float* Wa  = (const float*)d_in[9];
    const float* ba  = (const float*)d_in[10];
    const float* We  = (const float*)d_in[11];
    const float* be  = (const float*)d_in[12];
    const float* W3  = (const float*)d_in[13];
    const float* b3  = (const float*)d_in[14];
    const float* W4  = (const float*)d_in[15];
    const float* b4  = (const float*)d_in[16];

    float* out = (float*)d_out;
    float* out_recon = out;
    float* out_mu    = out_recon + (size_t)BATCH * 784;
    float* out_Q     = out_mu    + (size_t)BATCH * 100;
    float* out_a     = out_Q     + (size_t)BATCH * 2000;
    float* out_eig   = out_a     + (size_t)BATCH * 5;

    __nv_bfloat16 *xhi, *xlo, *h1hi, *h1lo, *h3hi, *h3lo;
    __nv_bfloat16 *B1hi, *B1lo, *BQhi, *BQlo, *Bmuhi, *Bmulo, *Behi, *Belo, *B4hi, *B4lo;
    float* zp;
    cudaGetSymbolAddress((void**)&xhi, g_xhi);
    cudaGetSymbolAddress((void**)&xlo, g_xlo);
    cudaGetSymbolAddress((void**)&h1hi, g_h1hi);
    cudaGetSymbolAddress((void**)&h1lo, g_h1lo);
    cudaGetSymbolAddress((void**)&h3hi, g_h3hi);
    cudaGetSymbolAddress((void**)&h3lo, g_h3lo);
    cudaGetSymbolAddress((void**)&B1hi, g_B1hi);
    cudaGetSymbolAddress((void**)&B1lo, g_B1lo);
    cudaGetSymbolAddress((void**)&BQhi, g_BQhi);
    cudaGetSymbolAddress((void**)&BQlo, g_BQlo);
    cudaGetSymbolAddress((void**)&Bmuhi, g_Bmuhi);
    cudaGetSymbolAddress((void**)&Bmulo, g_Bmulo);
    cudaGetSymbolAddress((void**)&Behi, g_Behi);
    cudaGetSymbolAddress((void**)&Belo, g_Belo);
    cudaGetSymbolAddress((void**)&B4hi, g_B4hi);
    cudaGetSymbolAddress((void**)&B4lo, g_B4lo);
    cudaGetSymbolAddress((void**)&zp, g_z);

    cudaFuncSetAttribute(mma_gemm<1, true>,  cudaFuncAttributeMaxDynamicSharedMemorySize, GEMM_SMEM);
    cudaFuncSetAttribute(mma_gemm<2, false>, cudaFuncAttributeMaxDynamicSharedMemorySize, GEMM_SMEM);
    cudaFuncSetAttribute(mma_gemm<0, false>, cudaFuncAttributeMaxDynamicSharedMemorySize, GEMM_SMEM);
    cudaFuncSetAttribute(mma_gemm<3, false>, cudaFuncAttributeMaxDynamicSharedMemorySize, GEMM_SMEM);

    // input / weight splits
    {
        long tot = (long)BATCH * KP_X;
        split_a<<<(unsigned)((tot + 255) / 256), 256>>>(x, xhi, xlo, 784, KP_X, tot);
    }
    split_w<<<(400 * KP_X + 255) / 256, 256>>>(W1, B1hi, B1lo, 784, 400, KP_X, 400);
    split_w<<<(2000 * KP_H + 255) / 256, 256>>>(WQ, BQhi, BQlo, 400, 2000, KP_H, 2000);
    split_w<<<(128 * KP_H + 255) / 256, 256>>>(Wmu, Bmuhi, Bmulo, 400, 100, KP_H, 128);
    split_w<<<(128 * KP_H + 255) / 256, 256>>>(We, Behi, Belo, 400, 100, KP_H, 128);
    split_w<<<(784 * KP_H + 255) / 256, 256>>>(W4, B4hi, B4lo, 400, 784, KP_H, 784);

    // h1 = relu(x@W1+b1) -> bf16 hi/lo (zero-pads cols 400..447)
    mma_gemm<1, true><<<dim3(4, 256), 256, GEMM_SMEM>>>(
        xhi, xlo, B1hi, B1lo, b1, nullptr, h1hi, h1lo, 400, KP_X, KP_H);
    // Q = exp(h1@WQ+bQ)
    mma_gemm<2, false><<<dim3(16, 256), 256, GEMM_SMEM>>>(
        h1hi, h1lo, BQhi, BQlo, bQ, out_Q, nullptr, nullptr, 2000, KP_H, 2000);
    // mu = h1@Wmu+bmu
    mma_gemm<0, false><<<dim3(1, 256), 256, GEMM_SMEM>>>(
        h1hi, h1lo, Bmuhi, Bmulo, bmu, out_mu, nullptr, nullptr, 100, KP_H, 100);
    // eigen = exp(h1@We+be)
    mma_gemm<2, false><<<dim3(1, 256), 256, GEMM_SMEM>>>(
        h1hi, h1lo, Behi, Belo, be, out_eig, nullptr, nullptr, 100, KP_H, 100);
    // softmax / idx / LU solve / z
    solve_kernel<<<BATCH / 8, 256>>>(Wa, ba, u, eps, h1hi, h1lo, out_Q, out_mu,
                                     out_eig, out_a, zp);
    // h3 = relu(z@W3+b3) -> bf16 hi/lo (zero-pads)
    h3_kernel<<<dim3(4, BATCH / 32), 128>>>(zp, W3, b3, h3hi, h3lo);
    // recon = sigmoid(h3@W4+b4)
    mma_gemm<3, false><<<dim3(7, 256), 256, GEMM_SMEM>>>(
        h3hi, h3lo, B4hi, B4lo, b4, out_recon, nullptr, nullptr, 784, KP_H, 784);
}

// round 4
// speedup vs baseline: 2.3032x; 1.0896x over previous
#include <cuda_runtime.h>
#include <cuda_bf16.h>
#include <math.h>
#include <stdint.h>

#define BATCH 32768
#define KP_X 832   // 784 padded to 26*32
#define KP_H 448   // 400 padded to 14*32

// ---------------- scratch (__device__ globals; no cudaMalloc allowed) ------
__device__ __align__(256) __nv_bfloat16 g_xhi[BATCH * KP_X];
__device__ __align__(256) __nv_bfloat16 g_xlo[BATCH * KP_X];
__device__ __align__(256) __nv_bfloat16 g_h1hi[BATCH * KP_H];
__device__ __align__(256) __nv_bfloat16 g_h1lo[BATCH * KP_H];
__device__ __align__(256) __nv_bfloat16 g_h3hi[BATCH * KP_H];
__device__ __align__(256) __nv_bfloat16 g_h3lo[BATCH * KP_H];
__device__ __align__(256) __nv_bfloat16 g_B1hi[400 * KP_X];
__device__ __align__(256) __nv_bfloat16 g_B1lo[400 * KP_X];
__device__ __align__(256) __nv_bfloat16 g_BQhi[2000 * KP_H];
__device__ __align__(256) __nv_bfloat16 g_BQlo[2000 * KP_H];
__device__ __align__(256) __nv_bfloat16 g_Bmehi[256 * KP_H];
__device__ __align__(256) __nv_bfloat16 g_Bmelo[256 * KP_H];
__device__ __align__(256) float g_bme[256];
__device__ __align__(256) __nv_bfloat16 g_B4hi[784 * KP_H];
__device__ __align__(256) __nv_bfloat16 g_B4lo[784 * KP_H];
__device__ float g_z[BATCH * 20];

// ---------------- helpers --------------------------------------------------
__device__ __forceinline__ uint32_t smem_u32(const void* p) {
    uint32_t a;
    asm("{ .reg .u64 t; cvta.to.shared.u64 t, %1; cvt.u32.u64 %0, t; }"
        : "=r"(a) : "l"(p));
    return a;
}
__device__ __forceinline__ void split2(float v, __nv_bfloat16& hi, __nv_bfloat16& lo) {
    hi = __float2bfloat16(v);
    lo = __float2bfloat16(v - __bfloat162float(hi));
}
template <int ACT>
__device__ __forceinline__ float act_apply(float v) {
    if (ACT == 1) return fmaxf(v, 0.f);
    if (ACT == 2) return expf(v);
    if (ACT == 3) return 1.f / (1.f + expf(-v));
    return v;
}

#define CP_ASYNC16(dst, src, sz) \
    asm volatile("cp.async.cg.shared.global [%0], [%1], 16, %2;" \
                 :: "r"(dst), "l"(src), "r"(sz) : "memory")
#define CP_COMMIT() asm volatile("cp.async.commit_group;" ::: "memory")
template <int NW>
__device__ __forceinline__ void cp_wait() {
    asm volatile("cp.async.wait_group %0;" :: "n"(NW) : "memory");
}

__device__ __forceinline__ void ldsm4(uint32_t* r, uint32_t addr) {
    asm volatile("ldmatrix.sync.aligned.m8n8.x4.shared.b16 {%0,%1,%2,%3}, [%4];"
                 : "=r"(r[0]), "=r"(r[1]), "=r"(r[2]), "=r"(r[3]) : "r"(addr));
}
__device__ __forceinline__ void mma16816(float* d, const uint32_t* a, const uint32_t* b) {
    asm volatile(
        "mma.sync.aligned.m16n8k16.row.col.f32.bf16.bf16.f32 "
        "{%0,%1,%2,%3}, {%4,%5,%6,%7}, {%8,%9}, {%0,%1,%2,%3};"
        : "+f"(d[0]), "+f"(d[1]), "+f"(d[2]), "+f"(d[3])
        : "r"(a[0]), "r"(a[1]), "r"(a[2]), "r"(a[3]), "r"(b[0]), "r"(b[1]));
}

// Row stride 64B (32 bf16); XOR-swizzle 16B chunks: chunkpos = chunk ^ ((row>>1)&3)
__device__ __forceinline__ uint32_t swoff(int row, int chunk) {
    return ((uint32_t)row << 6) + ((uint32_t)((chunk ^ ((row >> 1) & 3))) << 4);
}

// ---------------- split kernels -------------------------------------------
// x [B,784] fp32 -> hi/lo [B,KP_X] bf16, vectorized 4-wide
__global__ void split_a4(const float* __restrict__ A, __nv_bfloat16* __restrict__ hi,
                         __nv_bfloat16* __restrict__ lo) {
    const int per_row = KP_X / 4;  // 208
    long i = (long)blockIdx.x * blockDim.x + threadIdx.x;
    if (i >= (long)BATCH * per_row) return;
    int k4 = (int)(i % per_row);
    long r = i / per_row;
    int k = k4 * 4;
    float4 v = make_float4(0.f, 0.f, 0.f, 0.f);
    if (k < 784) v = *(const float4*)(A + r * 784 + k);
    __nv_bfloat16 h[4], l[4];
    split2(v.x, h[0], l[0]);
    split2(v.y, h[1], l[1]);
    split2(v.z, h[2], l[2]);
    split2(v.w, h[3], l[3]);
    *(uint2*)(hi + r * KP_X + k) = *(uint2*)h;
    *(uint2*)(lo + r * KP_X + k) = *(uint2*)l;
}

// W [K,N] fp32 -> out [Np,Kp] bf16 (transposed, padded), smem-tiled transpose
__global__ void __launch_bounds__(256)
split_wt(const float* __restrict__ W, __nv_bfloat16* __restrict__ hi,
         __nv_bfloat16* __restrict__ lo, int K, int N, int Kp, int Np) {
    __shared__ float s[32][33];
    const int tx = threadIdx.x & 31, ty = threadIdx.x >> 5;  // 32x8
    const int tileN = blockIdx.x * 32, tileK = blockIdx.y * 32;
#pragma unroll
    for (int r = 0; r < 4; r++) {
        int kk = tileK + ty + r * 8, nn = tileN + tx;
        s[ty + r * 8][tx] = (kk < K && nn < N) ? W[(size_t)kk * N + nn] : 0.f;
    }
    __syncthreads();
#pragma unroll
    for (int r = 0; r < 4; r++) {
        int nn = tileN + ty + r * 8, kk = tileK + tx;
        if (nn < Np && kk < Kp) {
            __nv_bfloat16 h, l;
            split2(s[tx][ty + r * 8], h, l);
            hi[(size_t)nn * Kp + kk] = h;
            lo[(size_t)nn * Kp + kk] = l;
        }
    }
}

// Build fused mu|eigen weight buffer [256,KP_H] + combined bias [256]
__global__ void prep_me(const float* __restrict__ Wmu, const float* __restrict__ bmu,
                        const float* __restrict__ We, const float* __restrict__ be,
                        __nv_bfloat16* __restrict__ hi, __nv_bfloat16* __restrict__ lo,
                        float* __restrict__ bias) {
    int i = blockIdx.x * blockDim.x + threadIdx.x;
    if (i < 256) {
        bias[i] = (i < 100) ? bmu[i] : ((i >= 128 && i < 228) ? be[i - 128] : 0.f);
    }
    if (i >= 256 * KP_H) return;
    int n = i / KP_H, k = i % KP_H;
    float v = 0.f;
    if (k < 400) {
        if (n < 100) v = Wmu[(size_t)k * 100 + n];
        else if (n >= 128 && n < 228) v = We[(size_t)k * 100 + (n - 128)];
    }
    __nv_bfloat16 h, l;
    split2(v, h, l);
    hi[i] = h;
    lo[i] = l;
}

// ---------------- 3-term bf16 split GEMM on mma.sync -----------------------
// C[M,N] = act((Ahi+Alo)[M,Kp] @ ((Bhi+Blo)[N,Kp])^T + bias)
// 128x128x32 CTA tile, 8 warps (4x2), warp tile 32x64, 3-stage cp.async.
// ACT==4: fused dual output (cols [0,100) -> C as mu; cols [128,228) -> C2 as exp)
#define STAGES 3
#define STAGE_BYTES 32768
#define GEMM_SMEM (STAGES * STAGE_BYTES)

template <int ACT, bool SPLIT_OUT>
__global__ void __launch_bounds__(256, 2)
mma_gemm(const __nv_bfloat16* __restrict__ Ahi, const __nv_bfloat16* __restrict__ Alo,
         const __nv_bfloat16* __restrict__ Bhi, const __nv_bfloat16* __restrict__ Blo,
         const float* __restrict__ bias, float* __restrict__ C, float* __restrict__ C2,
         __nv_bfloat16* __restrict__ outHi, __nv_bfloat16* __restrict__ outLo,
         int N, int Kp, int ldOut) {
    extern __shared__ char smem[];
    const uint32_t sbase = smem_u32(smem);
    const int tid = threadIdx.x, wid = tid >> 5, lane = tid & 31;
    const int wm = wid >> 1, wn = wid & 1;
    const int rowBase = blockIdx.y * 128, colBase = blockIdx.x * 128;
    const int NC = Kp >> 5;

    float acc[2][8][4];
#pragma unroll
    for (int i = 0; i < 2; i++)
#pragma unroll
        for (int j = 0; j < 8; j++)
#pragma unroll
            for (int q = 0; q < 4; q++) acc[i][j][q] = 0.f;

    auto load_stage = [&](int c, int stg) {
        const int kBase = c << 5;
        const uint32_t sb = sbase + stg * STAGE_BYTES;
#pragma unroll
        for (int t = 0; t < 4; t++) {
            const __nv_bfloat16* P = (t == 0) ? Ahi : (t == 1) ? Alo
                                   : (t == 2) ? Bhi : Blo;
            const bool isB = (t >= 2);
#pragma unroll
            for (int i = 0; i < 2; i++) {
                int cid = tid + i * 256;          // 0..511
                int row = cid >> 2, ch = cid & 3;
                uint32_t dst = sb + t * 8192 + swoff(row, ch);
                int gr, sz = 16;
                if (isB) {
                    gr = colBase + row;
                    if (gr >= N) { gr = 0; sz = 0; }
                } else {
                    gr = rowBase + row;
                }
                const void* src = P + (size_t)gr * Kp + kBase + ch * 8;
                CP_ASYNC16(dst, src, sz);
            }
        }
    };

    load_stage(0, 0);
    CP_COMMIT();
    load_stage(1, 1);
    CP_COMMIT();

    for (int c = 0; c < NC; c++) {
        cp_wait<STAGES - 2>();
        __syncthreads();
        if (c + STAGES - 1 < NC) {
            load_stage(c + STAGES - 1, (c + STAGES - 1) % STAGES);
            CP_COMMIT();
        }
        const uint32_t sb = sbase + (c % STAGES) * STAGE_BYTES;
#pragma unroll
        for (int kk = 0; kk < 2; kk++) {
            uint32_t ahi[2][4], alo[2][4];
#pragma unroll
            for (int mi = 0; mi < 2; mi++) {
                int row = wm * 32 + mi * 16 + (lane & 15);
                int ch = kk * 2 + (lane >> 4);
                uint32_t o = swoff(row, ch);
                ldsm4(ahi[mi], sb + o);
                ldsm4(alo[mi], sb + 8192 + o);
            }
#pragma unroll
            for (int bi = 0; bi < 4; bi++) {
                int row = wn * 64 + bi * 16 + (lane & 7) + ((lane >> 4) << 3);
                int ch = kk * 2 + ((lane >> 3) & 1);
                uint32_t o = swoff(row, ch);
                uint32_t bhi[4], blo[4];
                ldsm4(bhi, sb + 16384 + o);
                ldsm4(blo, sb + 24576 + o);
#pragma unroll
                for (int mi = 0; mi < 2; mi++) {
                    mma16816(acc[mi][2 * bi],     ahi[mi], bhi);
                    mma16816(acc[mi][2 * bi + 1], ahi[mi], bhi + 2);
                    mma16816(acc[mi][2 * bi],     alo[mi], bhi);
                    mma16816(acc[mi][2 * bi + 1], alo[mi], bhi + 2);
                    mma16816(acc[mi][2 * bi],     ahi[mi], blo);
                    mma16816(acc[mi][2 * bi + 1], ahi[mi], blo + 2);
                }
            }
        }
    }

    // ---------------- epilogue ----------------
#pragma unroll
    for (int mi = 0; mi < 2; mi++) {
#pragma unroll
        for (int ni = 0; ni < 8; ni++) {
            const float* a4 = acc[mi][ni];
            const int r0 = rowBase + wm * 32 + mi * 16 + (lane >> 2);
            const int col = colBase + wn * 64 + ni * 8 + ((lane & 3) << 1);
            float b0 = (col < N) ? bias[col] : 0.f;
            float b1 = (col + 1 < N) ? bias[col + 1] : 0.f;
#pragma unroll
            for (int h = 0; h < 2; h++) {
                const size_t row = (size_t)(r0 + h * 8);
                if (ACT == 4) {
                    float v0 = a4[2 * h + 0] + b0;
                    float v1 = a4[2 * h + 1] + b1;
                    if (col < 100) C[row * 100 + col] = v0;
                    else if (col >= 128 && col < 228) C2[row * 100 + col - 128] = expf(v0);
                    if (col + 1 < 100) C[row * 100 + col + 1] = v1;
                    else if (col + 1 >= 128 && col + 1 < 228) C2[row * 100 + col + 1 - 128] = expf(v1);
                    continue;
                }
                const float v0 = act_apply<ACT>(a4[2 * h + 0] + b0);
                const float v1 = act_apply<ACT>(a4[2 * h + 1] + b1);
                if (SPLIT_OUT) {
                    if (col < N) {
                        __nv_bfloat16 hh, ll;
                        split2(v0, hh, ll);
                        outHi[row * ldOut + col] = hh;
                        outLo[row * ldOut + col] = ll;
                        if (col + 1 < N) {
                            split2(v1, hh, ll);
                            outHi[row * ldOut + col + 1] = hh;
                            outLo[row * ldOut + col + 1] = ll;
                        } else if (col + 1 < ldOut) {
                            outHi[row * ldOut + col + 1] = __float2bfloat16(0.f);
                            outLo[row * ldOut + col + 1] = __float2bfloat16(0.f);
                        }
                    } else if (col < ldOut) {
                        outHi[row * ldOut + col] = __float2bfloat16(0.f);
                        outLo[row * ldOut + col] = __float2bfloat16(0.f);
                        if (col + 1 < ldOut) {
                            outHi[row * ldOut + col + 1] = __float2bfloat16(0.f);
                            outLo[row * ldOut + col + 1] = __float2bfloat16(0.f);
                        }
                    }
                } else {
                    if (col < N) C[row * ldOut + col] = v0;
                    if (col + 1 < N) C[row * ldOut + col + 1] = v1;
                }
            }
        }
    }
}

// ---------------- per-row solve kernel ------------------------------------
__global__ void __launch_bounds__(256)
solve_kernel(const float* __restrict__ Wa, const float* __restrict__ ba,
             const float* __restrict__ u, const float* __restrict__ eps,
             const __nv_bfloat16* __restrict__ h1hi, const __nv_bfloat16* __restrict__ h1lo,
             const float* __restrict__ outQ, const float* __restrict__ outMu,
             const float* __restrict__ outEig, float* __restrict__ outA,
             float* __restrict__ z) {
    __shared__ float Qs[8][400];
    const unsigned FULL = 0xffffffffu;
    const int w = threadIdx.x >> 5, lane = threadIdx.x & 31;
    const int row = blockIdx.x * 8 + w;

    float s0 = 0, s1 = 0, s2 = 0, s3 = 0, s4 = 0;
    const __nv_bfloat16* hh = h1hi + (size_t)row * KP_H;
    const __nv_bfloat16* hl = h1lo + (size_t)row * KP_H;
    for (int k = lane; k < 400; k += 32) {
        float h = __bfloat162float(hh[k]) + __bfloat162float(hl[k]);
        const float* wk = Wa + k * 5;
        s0 = fmaf(h, wk[0], s0);
        s1 = fmaf(h, wk[1], s1);
        s2 = fmaf(h, wk[2], s2);
        s3 = fmaf(h, wk[3], s3);
        s4 = fmaf(h, wk[4], s4);
    }
#pragma unroll
    for (int off = 16; off; off >>= 1) {
        s0 += __shfl_xor_sync(FULL, s0, off);
        s1 += __shfl_xor_sync(FULL, s1, off);
        s2 += __shfl_xor_sync(FULL, s2, off);
        s3 += __shfl_xor_sync(FULL, s3, off);
        s4 += __shfl_xor_sync(FULL, s4, off);
    }
    s0 += ba[0]; s1 += ba[1]; s2 += ba[2]; s3 += ba[3]; s4 += ba[4];
    float mx = fmaxf(fmaxf(fmaxf(s0, s1), fmaxf(s2, s3)), s4);
    float e0 = expf(s0 - mx), e1 = expf(s1 - mx), e2 = expf(s2 - mx),
          e3 = expf(s3 - mx), e4 = expf(s4 - mx);
    float inv = 1.f / (e0 + e1 + e2 + e3 + e4);
    float av[5] = {e0 * inv, e1 * inv, e2 * inv, e3 * inv, e4 * inv};
    if (lane == 0) {
        float* ar = outA + (size_t)row * 5;
        ar[0] = av[0]; ar[1] = av[1]; ar[2] = av[2]; ar[3] = av[3]; ar[4] = av[4];
    }

    float uu = u[row];
    int idx = 0;
    bool found = false;
    float c = 0.f;
#pragma unroll
    for (int j = 0; j < 5; j++) {
        c += av[j];
        if (!found && uu < c) { idx = j; found = true; }
    }

    const float* Qr = outQ + (size_t)row * 2000 + idx * 400;
    for (int k = lane; k < 400; k += 32) Qs[w][k] = Qr[k];
    __syncwarp();

    float o[20], r[20];
    float rhs = 0.f, eig = 0.f, mui = 0.f;
    if (lane < 20) {
#pragma unroll
        for (int j = 0; j < 20; j++) o[j] = Qs[w][lane * 20 + j];
        rhs = eps[(size_t)row * 20 + lane];
        eig = outEig[(size_t)row * 100 + idx * 20 + lane];
        mui = outMu[(size_t)row * 100 + idx * 20 + lane];
    } else {
#pragma unroll
        for (int j = 0; j < 20; j++) o[j] = 0.f;
    }
#pragma unroll
    for (int j = 0; j < 20; j++) r[j] = o[j];

#pragma unroll
    for (int k = 0; k < 20; k++) {
        float key = (lane >= k && lane < 20) ? fabsf(r[k]) : -1.0f;
        int pi = lane;
#pragma unroll
        for (int off = 16; off; off >>= 1) {
            float ok = __shfl_xor_sync(FULL, key, off);
            int oi = __shfl_xor_sync(FULL, pi, off);
            if (ok > key || (ok == key && oi < pi)) { key = ok; pi = oi; }
        }
        if (pi != k) {
            int partner = (lane == k) ? pi : ((lane == pi) ? k : lane);
#pragma unroll
            for (int j = 0; j < 20; j++) r[j] = __shfl_sync(FULL, r[j], partner);
            rhs = __shfl_sync(FULL, rhs, partner);
        }
        float akk = __shfl_sync(FULL, r[k], k);
        float m = (lane > k && lane < 20) ? r[k] / akk : 0.0f;
        float rk = __shfl_sync(FULL, rhs, k);
        rhs = fmaf(-m, rk, rhs);
#pragma unroll
        for (int j = k + 1; j < 20; j++) {
            float akj = __shfl_sync(FULL, r[j], k);
            r[j] = fmaf(-m, akj, r[j]);
        }
    }

    float y = 0.f;
#pragma unroll
    for (int k = 19; k >= 0; k--) {
        float num = __shfl_sync(FULL, rhs, k);
        float akk = __shfl_sync(FULL, r[k], k);
        float yk = num / akk;
        if (lane == k) y = yk;
        if (lane < k) rhs = fmaf(-r[k], yk, rhs);
    }

    float wv = eig * y;
    float zv = mui;
#pragma unroll
    for (int j = 0; j < 20; j++) {
        float wj = __shfl_sync(FULL, wv, j);
        zv = fmaf(o[j], wj, zv);
    }
    if (lane < 20) z[(size_t)row * 20 + lane] = zv;
}

// ---------------- h3 = relu(z@W3+b3) -> bf16 hi/lo (pads cols 400..447) ---
__global__ void __launch_bounds__(128)
h3_kernel(const float* __restrict__ z, const float* __restrict__ W3,
          const float* __restrict__ b3, __nv_bfloat16* __restrict__ h3hi,
          __nv_bfloat16* __restrict__ h3lo) {
    __shared__ float zs[32 * 20];
    const int col = blockIdx.x * 128 + threadIdx.x;
    const int row0 = blockIdx.y * 32;
    for (int i = threadIdx.x; i < 32 * 20; i += 128)
        zs[i] = z[(size_t)row0 * 20 + i];
    __syncthreads();

    if (col < KP_H) {
        if (col < 400) {
            float wcol[20];
#pragma unroll
            for (int k = 0; k < 20; k++) wcol[k] = W3[k * 400 + col];
            float bias = b3[col];
            for (int rr = 0; rr < 32; rr++) {
                float acc = bias;
#pragma unroll
                for (int k = 0; k < 20; k++)
                    acc = fmaf(zs[rr * 20 + k], wcol[k], acc);
                float v = fmaxf(acc, 0.f);
                __nv_bfloat16 h, l;
                split2(v, h, l);
                h3hi[(size_t)(row0 + rr) * KP_H + col] = h;
                h3lo[(size_t)(row0 + rr) * KP_H + col] = l;
            }
        } else {
            for (int rr = 0; rr < 32; rr++) {
                h3hi[(size_t)(row0 + rr) * KP_H + col] = __float2bfloat16(0.f);
                h3lo[(size_t)(row0 + rr) * KP_H + col] = __float2bfloat16(0.f);
            }
        }
    }
}

// ---------------- launch ---------------------------------------------------
extern "C" void kernel_launch(void* const* d_in, const int* in_sizes, int n_in,
                              void* d_out, int out_size) {
    const float* x   = (const float*)d_in[0];
    const float* u   = (const float*)d_in[1];
    const float* eps = (const float*)d_in[2];
    const float* W1  = (const float*)d_in[3];
    const float* b1  = (const float*)d_in[4];
    const float* Wmu = (const float*)d_in[5];
    const float* bmu = (const float*)d_in[6];
    const float* WQ  = (const float*)d_in[7];
    const float* bQ  = (const float*)d_in[8];
    const float* Wa  = (const float*)d_in[9];
    const float* ba  = (const float*)d_in[10];
    const float* We  = (const float*)d_in[11];
    const float* be  = (const float*)d_in[12];
    const float* W3  = (const float*)d_in[13];
    const float* b3  = (const float*)d_in[14];
    const float* W4  = (const float*)d_in[15];
    const float* b4  = (const float*)d_in[16];

    float* out = (float*)d_out;
    float* out_recon = out;
    float* out_mu    = out_recon + (size_t)BATCH * 784;
    float* out_Q     = out_mu    + (size_t)BATCH * 100;
    float* out_a     = out_Q     + (size_t)BATCH * 2000;
    float* out_eig   = out_a     + (size_t)BATCH * 5;

    __nv_bfloat16 *xhi, *xlo, *h1hi, *h1lo, *h3hi, *h3lo;
    __nv_bfloat16 *B1hi, *B1lo, *BQhi, *BQlo, *Bmehi, *Bmelo, *B4hi, *B4lo;
    float *zp, *bme;
    cudaGetSymbolAddress((void**)&xhi, g_xhi);
    cudaGetSymbolAddress((void**)&xlo, g_xlo);
    cudaGetSymbolAddress((void**)&h1hi, g_h1hi);
    cudaGetSymbolAddress((void**)&h1lo, g_h1lo);
    cudaGetSymbolAddress((void**)&h3hi, g_h3hi);
    cudaGetSymbolAddress((void**)&h3lo, g_h3lo);
    cudaGetSymbolAddress((void**)&B1hi, g_B1hi);
    cudaGetSymbolAddress((void**)&B1lo, g_B1lo);
    cudaGetSymbolAddress((void**)&BQhi, g_BQhi);
    cudaGetSymbolAddress((void**)&BQlo, g_BQlo);
    cudaGetSymbolAddress((void**)&Bmehi, g_Bmehi);
    cudaGetSymbolAddress((void**)&Bmelo, g_Bmelo);
    cudaGetSymbolAddress((void**)&bme, g_bme);
    cudaGetSymbolAddress((void**)&B4hi, g_B4hi);
    cudaGetSymbolAddress((void**)&B4lo, g_B4lo);
    cudaGetSymbolAddress((void**)&zp, g_z);

    cudaFuncSetAttribute(mma_gemm<1, true>,  cudaFuncAttributeMaxDynamicSharedMemorySize, GEMM_SMEM);
    cudaFuncSetAttribute(mma_gemm<2, false>, cudaFuncAttributeMaxDynamicSharedMemorySize, GEMM_SMEM);
    cudaFuncSetAttribute(mma_gemm<4, false>, cudaFuncAttributeMaxDynamicSharedMemorySize, GEMM_SMEM);
    cudaFuncSetAttribute(mma_gemm<3, false>, cudaFuncAttributeMaxDynamicSharedMemorySize, GEMM_SMEM);

    // #1 x split (vectorized)
    {
        long tot = (long)BATCH * (KP_X / 4);
        split_a4<<<(unsigned)((tot + 255) / 256), 256>>>(x, xhi, xlo);
    }
    // #2 W1 split (tiled transpose)
    split_wt<<<dim3((400 + 31) / 32, (KP_X + 31) / 32), 256>>>(W1, B1hi, B1lo, 784, 400, KP_X, 400);
    // #3 WQ split
    split_wt<<<dim3((2000 + 31) / 32, (KP_H + 31) / 32), 256>>>(WQ, BQhi, BQlo, 400, 2000, KP_H, 2000);
    // #4 fused mu|eigen weight + bias prep
    prep_me<<<(256 * KP_H + 255) / 256, 256>>>(Wmu, bmu, We, be, Bmehi, Bmelo, bme);
    // #5 h1 = relu(x@W1+b1) -> bf16 hi/lo
    mma_gemm<1, true><<<dim3(4, 256), 256, GEMM_SMEM>>>(
        xhi, xlo, B1hi, B1lo, b1, nullptr, nullptr, h1hi, h1lo, 400, KP_X, KP_H);
    // #6 Q = exp(h1@WQ+bQ)   <-- profiled launch (ncu -s 5 -c 1)
    mma_gemm<2, false><<<dim3(16, 256), 256, GEMM_SMEM>>>(
        h1hi, h1lo, BQhi, BQlo, bQ, out_Q, nullptr, nullptr, nullptr, 2000, KP_H, 2000);
    // #7 W4 split
    split_wt<<<dim3((784 + 31) / 32, (KP_H + 31) / 32), 256>>>(W4, B4hi, B4lo, 400, 784, KP_H, 784);
    // #8 fused mu + eigen GEMM (N=256)
    mma_gemm<4, false><<<dim3(2, 256), 256, GEMM_SMEM>>>(
        h1hi, h1lo, Bmehi, Bmelo, bme, out_mu, out_eig, nullptr, nullptr, 256, KP_H, 100);
    // #9 softmax / idx / LU solve / z
    solve_kernel<<<BATCH / 8, 256>>>(Wa, ba, u, eps, h1hi, h1lo, out_Q, out_mu,
                                     out_eig, out_a, zp);
    // #10 h3 = relu(z@W3+b3) -> bf16 hi/lo
    h3_kernel<<<dim3(4, BATCH / 32), 128>>>(zp, W3, b3, h3hi, h3lo);
    // #11 recon = sigmoid(h3@W4+b4)
    mma_gemm<3, false><<<dim3(7, 256), 256, GEMM_SMEM>>>(
        h3hi, h3lo, B4hi, B4lo, b4, out_recon, nullptr, nullptr, nullptr, 784, KP_H, 784);
}